// round 4
// baseline (speedup 1.0000x reference)
#include <cuda_runtime.h>
#include <math.h>

#define Bq   8
#define Nn   3136
#define C1d  64
#define C2d  128
#define KVd  192
#define Hh   4
#define MLPd 256
#define NROW (Bq*Nn)     /* 25088 */
#define NCH  49          /* 3136 / 64 */
#define GSZ  (C1d*KVd)   /* 12288 */

// ---------------- scratch (device globals; no allocation) ----------------
__device__ float g_ea[NROW*KVd];          // 19.3 MB  LN(concat) rows
__device__ float g_Gpart[Bq*NCH*GSZ];     // 19.3 MB  per-chunk partials of G
__device__ float g_G[Bq*GSZ];             //  G[b] = cx1^T @ ea
__device__ float g_S[Bq*Hh*GSZ];          //  scores (scaled, pre-IN)
__device__ float2 g_pstats[Bq*Hh*4];      //  per-tile (sum, sumsq) of scores
__device__ float g_Pp[Bq*Hh*GSZ];         //  probs @ Wv (per head)
__device__ float g_M[Bq*GSZ];             //  M[b] = Wout @ Pbar

extern __shared__ float dsm[];

// ============ 1) fused dual-LayerNorm + G partial ============
// grid (49, 8), 512 threads
__global__ __launch_bounds__(512,1) void gmatln_kernel(
        const float* __restrict__ emb1, const float* __restrict__ emb2,
        const float* __restrict__ g1, const float* __restrict__ b1,
        const float* __restrict__ gA, const float* __restrict__ bA) {
    float* sE = dsm;                 // [64][196] raw -> normalized ea
    float* sC = dsm + 64*196;        // [64][66]  cx1
    __shared__ float m1s[64], r1s[64], mAs[64], rAs[64];
    int ch = blockIdx.x, b = blockIdx.y;
    int base = b*Nn + ch*64;
    int tid = threadIdx.x;
    for (int i = tid; i < 64*KVd; i += 512) {
        int r = i / KVd, c = i % KVd;
        float v = (c < C1d) ? emb1[(size_t)(base+r)*C1d + c]
                            : emb2[(size_t)(base+r)*C2d + (c - C1d)];
        sE[r*196 + c] = v;
    }
    __syncthreads();
    if (tid < 64) {
        float s1 = 0.f, q1 = 0.f, s2 = 0.f, q2 = 0.f;
        const float* row = sE + tid*196;
        #pragma unroll 8
        for (int c = 0; c < C1d; c++)  { float v = row[c]; s1 += v; q1 += v*v; }
        #pragma unroll 8
        for (int c = C1d; c < KVd; c++){ float v = row[c]; s2 += v; q2 += v*v; }
        float m1 = s1 * (1.f/C1d);
        float v1 = q1 * (1.f/C1d) - m1*m1;
        m1s[tid] = m1; r1s[tid] = rsqrtf(v1 + 1e-6f);
        float mA = (s1+s2) * (1.f/KVd);
        float vA = (q1+q2) * (1.f/KVd) - mA*mA;
        mAs[tid] = mA; rAs[tid] = rsqrtf(vA + 1e-6f);
    }
    __syncthreads();
    for (int i = tid; i < 64*KVd; i += 512) {
        int r = i / KVd, c = i % KVd;
        float v = sE[r*196 + c];
        float ea = (v - mAs[r]) * rAs[r] * __ldg(gA + c) + __ldg(bA + c);
        sE[r*196 + c] = ea;
        g_ea[(size_t)(base+r)*KVd + c] = ea;
        if (c < C1d)
            sC[r*66 + c] = (v - m1s[r]) * r1s[r] * __ldg(g1 + c) + __ldg(b1 + c);
    }
    __syncthreads();
    int x = tid & 15, y = tid >> 4;        // y 0..31
    int cs = y*2, ks = x*12;
    float acc[2][12];
    #pragma unroll
    for (int j = 0; j < 2; j++)
        #pragma unroll
        for (int l = 0; l < 12; l++) acc[j][l] = 0.f;
    for (int r = 0; r < 64; r++) {
        float af[2];
        #pragma unroll
        for (int j = 0; j < 2; j++) af[j] = sC[r*66 + cs + j];
        const float4* gp = (const float4*)(sE + r*196 + ks);
        float4 b0 = gp[0], b1v = gp[1], b2 = gp[2];
        float bf[12] = {b0.x,b0.y,b0.z,b0.w, b1v.x,b1v.y,b1v.z,b1v.w, b2.x,b2.y,b2.z,b2.w};
        #pragma unroll
        for (int j = 0; j < 2; j++)
            #pragma unroll
            for (int l = 0; l < 12; l++) acc[j][l] += af[j]*bf[l];
    }
    float* out = g_Gpart + (size_t)(b*NCH + ch)*GSZ;
    #pragma unroll
    for (int j = 0; j < 2; j++)
        #pragma unroll
        for (int l = 0; l < 12; l++) out[(cs+j)*KVd + ks + l] = acc[j][l];
}

// ============ 2) reduce chunk partials ============
__global__ void gred_kernel() {
    int idx = blockIdx.x*256 + threadIdx.x;
    int b = idx / GSZ, e = idx % GSZ;
    const float* p = g_Gpart + (size_t)b*NCH*GSZ + e;
    float s = 0.f;
    #pragma unroll 7
    for (int ch = 0; ch < NCH; ch++) s += p[ch*GSZ];
    g_G[idx] = s;
}

// ============ 3) fused T=Wq@G, S-tile = T@Wk^T/sqrt(KV) + partial stats =====
// grid (32, 4), 512 threads
__global__ __launch_bounds__(512,1) void smatT_kernel(
        const float* __restrict__ Wq, const float* __restrict__ Wk) {
    float* sG  = dsm;                  // [64][196]
    float* sT  = dsm + 64*196;         // [64][196]
    float* sWq = sT + 64*196;          // [64][68]  Wq^T (c-major)
    float* sWk = sWq + 64*68;          // [48][197]
    __shared__ float redS[16], redQ[16];
    int bh = blockIdx.x, tile = blockIdx.y;
    int b = bh >> 2, h = bh & 3;
    int tid = threadIdx.x;
    for (int i = tid; i < GSZ; i += 512) {
        int c = i / KVd, k = i % KVd;
        sG[c*196 + k] = g_G[(size_t)b*GSZ + i];
    }
    for (int i = tid; i < C1d*C1d; i += 512) {
        int d = i >> 6, c = i & 63;
        sWq[c*68 + d] = Wq[(size_t)h*C1d*C1d + i];
    }
    for (int i = tid; i < 48*KVd; i += 512) {
        int r = i / KVd, k = i % KVd;
        sWk[r*197 + k] = Wk[(size_t)h*KVd*KVd + (tile*48 + r)*KVd + k];
    }
    __syncthreads();
    int x = tid & 15, y = tid >> 4;        // y 0..31
    // Phase 1: T = Wq @ G, tile 2d x 12k
    {
        int ds = y*2, ks = x*12;
        float acc[2][12];
        #pragma unroll
        for (int j = 0; j < 2; j++)
            #pragma unroll
            for (int l = 0; l < 12; l++) acc[j][l] = 0.f;
        for (int c = 0; c < C1d; c++) {
            float wf[2];
            #pragma unroll
            for (int j = 0; j < 2; j++) wf[j] = sWq[c*68 + ds + j];
            const float4* gp = (const float4*)(sG + c*196 + ks);
            float4 g0 = gp[0], g1 = gp[1], g2 = gp[2];
            float gf[12] = {g0.x,g0.y,g0.z,g0.w, g1.x,g1.y,g1.z,g1.w, g2.x,g2.y,g2.z,g2.w};
            #pragma unroll
            for (int j = 0; j < 2; j++)
                #pragma unroll
                for (int l = 0; l < 12; l++) acc[j][l] += wf[j]*gf[l];
        }
        #pragma unroll
        for (int j = 0; j < 2; j++) {
            float4* tp = (float4*)(sT + (ds+j)*196 + ks);
            tp[0] = make_float4(acc[j][0],acc[j][1],acc[j][2],acc[j][3]);
            tp[1] = make_float4(acc[j][4],acc[j][5],acc[j][6],acc[j][7]);
            tp[2] = make_float4(acc[j][8],acc[j][9],acc[j][10],acc[j][11]);
        }
    }
    __syncthreads();
    // Phase 2: S tile = T @ Wk^T * scale, tile 2c x 3k2
    const float scale = 0.0721687836487f;   // 1/sqrt(192)
    int cs = y*2, kl = x*3;
    float acc2[2][3];
    #pragma unroll
    for (int j = 0; j < 2; j++)
        #pragma unroll
        for (int l = 0; l < 3; l++) acc2[j][l] = 0.f;
    for (int kp = 0; kp < KVd; kp++) {
        float tf[2], wf[3];
        #pragma unroll
        for (int j = 0; j < 2; j++) tf[j] = sT[(cs+j)*196 + kp];
        #pragma unroll
        for (int l = 0; l < 3; l++) wf[l] = sWk[(kl+l)*197 + kp];
        #pragma unroll
        for (int j = 0; j < 2; j++)
            #pragma unroll
            for (int l = 0; l < 3; l++) acc2[j][l] += tf[j]*wf[l];
    }
    float lsum = 0.f, lsq = 0.f;
    float* out = g_S + (size_t)bh*GSZ;
    #pragma unroll
    for (int j = 0; j < 2; j++)
        #pragma unroll
        for (int l = 0; l < 3; l++) {
            float v = acc2[j][l]*scale;
            out[(cs+j)*KVd + tile*48 + kl + l] = v;
            lsum += v; lsq += v*v;
        }
    int w = tid >> 5, lane = tid & 31;
    #pragma unroll
    for (int o = 16; o > 0; o >>= 1) {
        lsum += __shfl_down_sync(0xffffffffu, lsum, o);
        lsq  += __shfl_down_sync(0xffffffffu, lsq, o);
    }
    if (lane == 0) { redS[w] = lsum; redQ[w] = lsq; }
    __syncthreads();
    if (tid == 0) {
        float s = 0.f, q = 0.f;
        #pragma unroll
        for (int i = 0; i < 16; i++) { s += redS[i]; q += redQ[i]; }
        g_pstats[bh*4 + tile] = make_float2(s, q);
    }
}

// ============ 4) fused InstanceNorm + softmax + Pp-tile = probs @ Wv ========
// grid (32, 4), 512 threads
__global__ __launch_bounds__(512,1) void pmat_kernel(const float* __restrict__ Wv) {
    float* sS = dsm;                   // [64][196] scores -> probs
    float* sV = dsm + 64*196;          // [192][52]
    __shared__ float s_m, s_rs;
    int bh = blockIdx.x, h = bh & 3, tile = blockIdx.y;
    int tid = threadIdx.x;
    for (int i = tid; i < GSZ; i += 512) {
        int c = i / KVd, k = i % KVd;
        sS[c*196 + k] = g_S[(size_t)bh*GSZ + i];
    }
    for (int i = tid; i < KVd*48; i += 512) {
        int k = i / 48, col = i % 48;
        sV[k*52 + col] = Wv[(size_t)h*KVd*KVd + k*KVd + tile*48 + col];
    }
    if (tid == 0) {
        float s = 0.f, q = 0.f;
        #pragma unroll
        for (int t = 0; t < 4; t++) {
            float2 p = g_pstats[bh*4 + t];
            s += p.x; q += p.y;
        }
        float m = s * (1.f/GSZ);
        float v = q * (1.f/GSZ) - m*m;
        s_m = m; s_rs = rsqrtf(v + 1e-5f);
    }
    __syncthreads();
    float mean = s_m, rs = s_rs;
    int w = tid >> 5, lane = tid & 31;
    for (int r = w; r < C1d; r += 16) {
        float vals[6];
        float mx = -1e30f;
        #pragma unroll
        for (int mm = 0; mm < 6; mm++) {
            vals[mm] = (sS[r*196 + lane + 32*mm] - mean) * rs;
            mx = fmaxf(mx, vals[mm]);
        }
        #pragma unroll
        for (int o = 16; o > 0; o >>= 1) mx = fmaxf(mx, __shfl_xor_sync(0xffffffffu, mx, o));
        float es = 0.f;
        #pragma unroll
        for (int mm = 0; mm < 6; mm++) { vals[mm] = __expf(vals[mm] - mx); es += vals[mm]; }
        #pragma unroll
        for (int o = 16; o > 0; o >>= 1) es += __shfl_xor_sync(0xffffffffu, es, o);
        float inv = 1.f / es;
        #pragma unroll
        for (int mm = 0; mm < 6; mm++) sS[r*196 + lane + 32*mm] = vals[mm] * inv;
    }
    __syncthreads();
    int x = tid & 15, y = tid >> 4;
    int cs = y*2, kl = x*3;
    float acc[2][3];
    #pragma unroll
    for (int j = 0; j < 2; j++)
        #pragma unroll
        for (int l = 0; l < 3; l++) acc[j][l] = 0.f;
    for (int kp = 0; kp < KVd; kp++) {
        float pf[2], vf[3];
        #pragma unroll
        for (int j = 0; j < 2; j++) pf[j] = sS[(cs+j)*196 + kp];
        #pragma unroll
        for (int l = 0; l < 3; l++) vf[l] = sV[kp*52 + kl + l];
        #pragma unroll
        for (int j = 0; j < 2; j++)
            #pragma unroll
            for (int l = 0; l < 3; l++) acc[j][l] += pf[j]*vf[l];
    }
    float* out = g_Pp + (size_t)bh*GSZ;
    #pragma unroll
    for (int j = 0; j < 2; j++)
        #pragma unroll
        for (int l = 0; l < 3; l++)
            out[(cs+j)*KVd + tile*48 + kl + l] = acc[j][l];
}

// ============ 5) M[b] = Wout @ mean_h(Pp) ============
__global__ __launch_bounds__(512,1) void mmat_kernel(const float* __restrict__ Wout) {
    float* sP = dsm;                 // [64][196]
    float* sW = dsm + 64*196;        // [64][64]
    int b = blockIdx.x;
    int tid = threadIdx.x;
    for (int i = tid; i < GSZ; i += 512) {
        int c = i / KVd, k = i % KVd;
        float sum = g_Pp[(size_t)(b*Hh+0)*GSZ + i] + g_Pp[(size_t)(b*Hh+1)*GSZ + i]
                  + g_Pp[(size_t)(b*Hh+2)*GSZ + i] + g_Pp[(size_t)(b*Hh+3)*GSZ + i];
        sP[c*196 + k] = sum * 0.25f;
    }
    for (int i = tid; i < C1d*C1d; i += 512) sW[i] = Wout[i];
    __syncthreads();
    int x = tid & 15, y = tid >> 4;
    int ds = y*2, ks = x*12;
    float acc[2][12];
    #pragma unroll
    for (int j = 0; j < 2; j++)
        #pragma unroll
        for (int l = 0; l < 12; l++) acc[j][l] = 0.f;
    for (int c = 0; c < 64; c++) {
        float wf[2];
        #pragma unroll
        for (int j = 0; j < 2; j++) wf[j] = sW[(ds+j)*C1d + c];
        const float4* pp = (const float4*)(sP + c*196 + ks);
        float4 p0 = pp[0], p1 = pp[1], p2 = pp[2];
        float pf[12] = {p0.x,p0.y,p0.z,p0.w, p1.x,p1.y,p1.z,p1.w, p2.x,p2.y,p2.z,p2.w};
        #pragma unroll
        for (int j = 0; j < 2; j++)
            #pragma unroll
            for (int l = 0; l < 12; l++) acc[j][l] += wf[j]*pf[l];
    }
    float* out = g_M + (size_t)b*GSZ;
    #pragma unroll
    for (int j = 0; j < 2; j++)
        #pragma unroll
        for (int l = 0; l < 12; l++) out[(ds+j)*KVd + ks + l] = acc[j][l];
}

// ============ 6) fused tail: cx = emb1 + ea@M^T ; out = FFN(cx) + cx ========
__device__ __forceinline__ float gelu_exact(float x) {
    return 0.5f * x * (1.f + erff(x * 0.70710678118654752f));
}

// smem float offsets
#define T_HS   0                      /* Hs [64][260]=16640 ; alias sEA [64][196]=12544 */
#define T_W1   16640                  /* W1 [64][260]=16640 ; alias sMt [192][68]=13056 */
#define T_W2   33280                  /* W2 [256][68]=17408 */
#define T_XN   50688                  /* Xn [64][68] =4352  */
#define T_TOT  55040                  /* *4 = 220160 B */

__global__ __launch_bounds__(512,1) void tail_kernel(
        const float* __restrict__ emb1,
        const float* __restrict__ fc1w, const float* __restrict__ fc1b,
        const float* __restrict__ fc2w, const float* __restrict__ fc2b,
        const float* __restrict__ fg, const float* __restrict__ fb,
        float* __restrict__ out) {
    float* sEA = dsm + T_HS;           // [64][196]
    float* sMt = dsm + T_W1;           // [192][68]  M^T
    float* W2s = dsm + T_W2;           // [256][68]  fc2^T (k-major rows)
    float* W1s = dsm + T_W1;           // [64][260]  (k-major rows, after octx)
    float* Hs  = dsm + T_HS;           // [64][260]  (after octx)
    float* Xn  = dsm + T_XN;           // [64][68]
    __shared__ float ms[64], rss[64];
    int ch = blockIdx.x, b = blockIdx.y;
    int base = b*Nn + ch*64;
    int tid = threadIdx.x;
    int x = tid & 15, y = tid >> 4;    // y 0..31
    for (int i = tid; i < 64*KVd; i += 512) {
        int r = i / KVd, k = i % KVd;
        sEA[r*196 + k] = g_ea[(size_t)base*KVd + i];
    }
    for (int i = tid; i < GSZ; i += 512) {
        int c = i / KVd, k = i % KVd;
        sMt[k*68 + c] = g_M[(size_t)b*GSZ + i];
    }
    for (int i = tid; i < C1d*MLPd; i += 512) {
        int c = i >> 8, k = i & 255;
        W2s[k*68 + c] = fc2w[i];
    }
    __syncthreads();
    // octx: cx tile (2x4) in registers, k-pair vectorized
    float cx[2][4];
    {
        int rs = y*2, cs = x*4;
        float acc[2][4];
        #pragma unroll
        for (int i = 0; i < 2; i++)
            #pragma unroll
            for (int j = 0; j < 4; j++) acc[i][j] = 0.f;
        for (int k = 0; k < KVd; k += 2) {
            float2 e0 = *(const float2*)(sEA + (rs+0)*196 + k);
            float2 e1 = *(const float2*)(sEA + (rs+1)*196 + k);
            float4 m0 = *(const float4*)(sMt + k*68 + cs);
            float4 m1 = *(const float4*)(sMt + (k+1)*68 + cs);
            acc[0][0] += e0.x*m0.x + e0.y*m1.x;
            acc[0][1] += e0.x*m0.y + e0.y*m1.y;
            acc[0][2] += e0.x*m0.z + e0.y*m1.z;
            acc[0][3] += e0.x*m0.w + e0.y*m1.w;
            acc[1][0] += e1.x*m0.x + e1.y*m1.x;
            acc[1][1] += e1.x*m0.y + e1.y*m1.y;
            acc[1][2] += e1.x*m0.z + e1.y*m1.z;
            acc[1][3] += e1.x*m0.w + e1.y*m1.w;
        }
        #pragma unroll
        for (int i = 0; i < 2; i++) {
            float4 e = *(const float4*)(emb1 + (size_t)(base+rs+i)*C1d + cs);
            cx[i][0] = e.x + acc[i][0];
            cx[i][1] = e.y + acc[i][1];
            cx[i][2] = e.z + acc[i][2];
            cx[i][3] = e.w + acc[i][3];
            *(float4*)(Xn + (rs+i)*68 + cs) = make_float4(cx[i][0],cx[i][1],cx[i][2],cx[i][3]);
        }
    }
    __syncthreads();
    // load W1 (k-major, overwrites sMt region); LN stats
    for (int i = tid; i < MLPd*C1d; i += 512) {
        int d = i >> 6, k = i & 63;
        W1s[k*260 + d] = fc1w[i];
    }
    if (tid < 64) {
        float s = 0.f, q = 0.f;
        const float* row = Xn + tid*68;
        #pragma unroll 8
        for (int c = 0; c < C1d; c++) { float v = row[c]; s += v; q += v*v; }
        float m = s * (1.f/C1d);
        float v = q * (1.f/C1d) - m*m;
        ms[tid] = m; rss[tid] = rsqrtf(v + 1e-6f);
    }
    __syncthreads();
    for (int i = tid; i < 64*C1d; i += 512) {
        int r = i >> 6, c = i & 63;
        Xn[r*68 + c] = (Xn[r*68 + c] - ms[r]) * rss[r] * __ldg(fg + c) + __ldg(fb + c);
    }
    __syncthreads();
    // fc1 + gelu: 2 rows x (4 groups of float4 cols)
    {
        int rs = y*2;
        float acc[2][16];
        #pragma unroll
        for (int i = 0; i < 2; i++)
            #pragma unroll
            for (int j = 0; j < 16; j++) acc[i][j] = 0.f;
        for (int k = 0; k < C1d; k++) {
            float x0 = Xn[(rs+0)*68 + k];
            float x1 = Xn[(rs+1)*68 + k];
            #pragma unroll
            for (int jj = 0; jj < 4; jj++) {
                float4 wv = *(const float4*)(W1s + k*260 + x*4 + 64*jj);
                acc[0][jj*4+0] += x0*wv.x; acc[0][jj*4+1] += x0*wv.y;
                acc[0][jj*4+2] += x0*wv.z; acc[0][jj*4+3] += x0*wv.w;
                acc[1][jj*4+0] += x1*wv.x; acc[1][jj*4+1] += x1*wv.y;
                acc[1][jj*4+2] += x1*wv.z; acc[1][jj*4+3] += x1*wv.w;
            }
        }
        #pragma unroll
        for (int jj = 0; jj < 4; jj++) {
            int col = x*4 + 64*jj;
            float4 bj = *(const float4*)(fc1b + col);
            #pragma unroll
            for (int i = 0; i < 2; i++) {
                float4 hv;
                hv.x = gelu_exact(acc[i][jj*4+0] + bj.x);
                hv.y = gelu_exact(acc[i][jj*4+1] + bj.y);
                hv.z = gelu_exact(acc[i][jj*4+2] + bj.z);
                hv.w = gelu_exact(acc[i][jj*4+3] + bj.w);
                *(float4*)(Hs + (rs+i)*260 + col) = hv;
            }
        }
    }
    __syncthreads();
    // fc2 + bias + residual, k-pair vectorized
    {
        int rs = y*2, cs = x*4;
        float acc[2][4];
        #pragma unroll
        for (int i = 0; i < 2; i++)
            #pragma unroll
            for (int j = 0; j < 4; j++) acc[i][j] = 0.f;
        for (int k = 0; k < MLPd; k += 2) {
            float2 h0 = *(const float2*)(Hs + (rs+0)*260 + k);
            float2 h1 = *(const float2*)(Hs + (rs+1)*260 + k);
            float4 w0 = *(const float4*)(W2s + k*68 + cs);
            float4 w1 = *(const float4*)(W2s + (k+1)*68 + cs);
            acc[0][0] += h0.x*w0.x + h0.y*w1.x;
            acc[0][1] += h0.x*w0.y + h0.y*w1.y;
            acc[0][2] += h0.x*w0.z + h0.y*w1.z;
            acc[0][3] += h0.x*w0.w + h0.y*w1.w;
            acc[1][0] += h1.x*w0.x + h1.y*w1.x;
            acc[1][1] += h1.x*w0.y + h1.y*w1.y;
            acc[1][2] += h1.x*w0.z + h1.y*w1.z;
            acc[1][3] += h1.x*w0.w + h1.y*w1.w;
        }
        float4 b2 = *(const float4*)(fc2b + cs);
        #pragma unroll
        for (int i = 0; i < 2; i++) {
            float4 o;
            o.x = acc[i][0] + b2.x + cx[i][0];
            o.y = acc[i][1] + b2.y + cx[i][1];
            o.z = acc[i][2] + b2.z + cx[i][2];
            o.w = acc[i][3] + b2.w + cx[i][3];
            *(float4*)(out + (size_t)(base+rs+i)*C1d + cs) = o;
        }
    }
}

// ---------------- launch ----------------
extern "C" void kernel_launch(void* const* d_in, const int* in_sizes, int n_in,
                              void* d_out, int out_size) {
    const float* emb1   = (const float*)d_in[0];
    const float* emb2   = (const float*)d_in[1];
    const float* Wq     = (const float*)d_in[2];
    const float* Wk     = (const float*)d_in[3];
    const float* Wv     = (const float*)d_in[4];
    const float* Wout   = (const float*)d_in[5];
    const float* ln1_g  = (const float*)d_in[6];
    const float* ln1_b  = (const float*)d_in[7];
    const float* lnA_g  = (const float*)d_in[8];
    const float* lnA_b  = (const float*)d_in[9];
    const float* ffn_g  = (const float*)d_in[10];
    const float* ffn_b  = (const float*)d_in[11];
    const float* fc1_w  = (const float*)d_in[12];
    const float* fc1_b  = (const float*)d_in[13];
    const float* fc2_w  = (const float*)d_in[14];
    const float* fc2_b  = (const float*)d_in[15];
    float* out = (float*)d_out;

    const int smem_gmatln = (64*196 + 64*66) * 4;                    // 67072
    const int smem_smatT  = (64*196 + 64*196 + 64*68 + 48*197) * 4;  // 155584
    const int smem_pmat   = (64*196 + 192*52) * 4;                   // 90112
    const int smem_mmat   = (64*196 + 64*64) * 4;                    // 66560
    const int smem_tail   = T_TOT * 4;                               // 220160

    cudaFuncSetAttribute(gmatln_kernel, cudaFuncAttributeMaxDynamicSharedMemorySize, smem_gmatln);
    cudaFuncSetAttribute(smatT_kernel,  cudaFuncAttributeMaxDynamicSharedMemorySize, smem_smatT);
    cudaFuncSetAttribute(pmat_kernel,   cudaFuncAttributeMaxDynamicSharedMemorySize, smem_pmat);
    cudaFuncSetAttribute(mmat_kernel,   cudaFuncAttributeMaxDynamicSharedMemorySize, smem_mmat);
    cudaFuncSetAttribute(tail_kernel,   cudaFuncAttributeMaxDynamicSharedMemorySize, smem_tail);

    gmatln_kernel<<<dim3(NCH, Bq), 512, smem_gmatln>>>(emb1, emb2, ln1_g, ln1_b, lnA_g, lnA_b);
    gred_kernel<<<(Bq*GSZ)/256, 256>>>();
    smatT_kernel<<<dim3(Bq*Hh, 4), 512, smem_smatT>>>(Wq, Wk);
    pmat_kernel<<<dim3(Bq*Hh, 4), 512, smem_pmat>>>(Wv);
    mmat_kernel<<<Bq, 512, smem_mmat>>>(Wout);
    tail_kernel<<<dim3(NCH, Bq), 512, smem_tail>>>(emb1, fc1_w, fc1_b, fc2_w, fc2_b, ffn_g, ffn_b, out);
}

// round 5
// speedup vs baseline: 1.2787x; 1.2787x over previous
#include <cuda_runtime.h>
#include <math.h>
#include <stdint.h>

#define Bq   8
#define Nn   3136
#define C1d  64
#define C2d  128
#define KVd  192
#define Hh   4
#define MLPd 256
#define NROW (Bq*Nn)     /* 25088 */
#define NCH  49          /* 3136 / 64 */
#define GSZ  (C1d*KVd)   /* 12288 */

// ---------------- scratch (device globals; no allocation) ----------------
__device__ float g_ea[NROW*KVd];          // 19.3 MB  LN(concat) rows
__device__ float g_Gpart[Bq*NCH*GSZ];     // 19.3 MB  per-chunk partials of G
__device__ float g_G[Bq*GSZ];             //  G[b] = cx1^T @ ea
__device__ float g_S[Bq*Hh*GSZ];          //  scores (scaled, pre-IN)
__device__ float2 g_pstats[Bq*Hh*4];      //  per-tile (sum, sumsq) of scores
__device__ float g_Pp[Bq*Hh*GSZ];         //  probs @ Wv (per head)
__device__ float g_M[Bq*GSZ];             //  M[b] = Wout @ Pbar

extern __shared__ float dsm[];

// ---------------- tf32 mma helpers ----------------
__device__ __forceinline__ uint32_t f2tf32(float f) {
    uint32_t u;
    asm("cvt.rna.tf32.f32 %0, %1;" : "=r"(u) : "f"(f));
    return u;
}
__device__ __forceinline__ void mma_tf32(float* c, const uint32_t* a, const uint32_t* b) {
    asm volatile("mma.sync.aligned.m16n8k8.row.col.f32.tf32.tf32.f32 "
        "{%0,%1,%2,%3}, {%4,%5,%6,%7}, {%8,%9}, {%0,%1,%2,%3};"
        : "+f"(c[0]), "+f"(c[1]), "+f"(c[2]), "+f"(c[3])
        : "r"(a[0]), "r"(a[1]), "r"(a[2]), "r"(a[3]), "r"(b[0]), "r"(b[1]));
}

// ============ 1) fused dual-LayerNorm + G partial (R3 config) ============
__global__ __launch_bounds__(256,1) void gmatln_kernel(
        const float* __restrict__ emb1, const float* __restrict__ emb2,
        const float* __restrict__ g1, const float* __restrict__ b1,
        const float* __restrict__ gA, const float* __restrict__ bA) {
    float* sE = dsm;                 // [64][193] raw -> normalized ea
    float* sC = dsm + 64*193;        // [64][65]  cx1
    __shared__ float m1s[64], r1s[64], mAs[64], rAs[64];
    int ch = blockIdx.x, b = blockIdx.y;
    int base = b*Nn + ch*64;
    int tid = threadIdx.x;
    for (int i = tid; i < 64*KVd; i += 256) {
        int r = i / KVd, c = i % KVd;
        float v = (c < C1d) ? emb1[(size_t)(base+r)*C1d + c]
                            : emb2[(size_t)(base+r)*C2d + (c - C1d)];
        sE[r*193 + c] = v;
    }
    __syncthreads();
    if (tid < 64) {
        float s1 = 0.f, q1 = 0.f, s2 = 0.f, q2 = 0.f;
        const float* row = sE + tid*193;
        #pragma unroll 8
        for (int c = 0; c < C1d; c++)  { float v = row[c]; s1 += v; q1 += v*v; }
        #pragma unroll 8
        for (int c = C1d; c < KVd; c++){ float v = row[c]; s2 += v; q2 += v*v; }
        float m1 = s1 * (1.f/C1d);
        float v1 = q1 * (1.f/C1d) - m1*m1;
        m1s[tid] = m1; r1s[tid] = rsqrtf(v1 + 1e-6f);
        float mA = (s1+s2) * (1.f/KVd);
        float vA = (q1+q2) * (1.f/KVd) - mA*mA;
        mAs[tid] = mA; rAs[tid] = rsqrtf(vA + 1e-6f);
    }
    __syncthreads();
    for (int i = tid; i < 64*KVd; i += 256) {
        int r = i / KVd, c = i % KVd;
        float v = sE[r*193 + c];
        float ea = (v - mAs[r]) * rAs[r] * __ldg(gA + c) + __ldg(bA + c);
        sE[r*193 + c] = ea;
        g_ea[(size_t)(base+r)*KVd + c] = ea;
        if (c < C1d)
            sC[r*65 + c] = (v - m1s[r]) * r1s[r] * __ldg(g1 + c) + __ldg(b1 + c);
    }
    __syncthreads();
    int x = tid & 15, y = tid >> 4;
    int cs = y*4, ks = x*12;
    float acc[4][12];
    #pragma unroll
    for (int j = 0; j < 4; j++)
        #pragma unroll
        for (int l = 0; l < 12; l++) acc[j][l] = 0.f;
    for (int r = 0; r < 64; r++) {
        float af[4], bf[12];
        #pragma unroll
        for (int j = 0; j < 4; j++) af[j] = sC[r*65 + cs + j];
        #pragma unroll
        for (int l = 0; l < 12; l++) bf[l] = sE[r*193 + ks + l];
        #pragma unroll
        for (int j = 0; j < 4; j++)
            #pragma unroll
            for (int l = 0; l < 12; l++) acc[j][l] += af[j]*bf[l];
    }
    float* out = g_Gpart + (size_t)(b*NCH + ch)*GSZ;
    #pragma unroll
    for (int j = 0; j < 4; j++)
        #pragma unroll
        for (int l = 0; l < 12; l++) out[(cs+j)*KVd + ks + l] = acc[j][l];
}

// ============ 2) reduce chunk partials ============
__global__ void gred_kernel() {
    int idx = blockIdx.x*256 + threadIdx.x;
    int b = idx / GSZ, e = idx % GSZ;
    const float* p = g_Gpart + (size_t)b*NCH*GSZ + e;
    float s = 0.f;
    #pragma unroll 7
    for (int ch = 0; ch < NCH; ch++) s += p[ch*GSZ];
    g_G[idx] = s;
}

// ============ 3) fused T=Wq@G, S-tile = T@Wk^T/sqrt(KV) + partial stats =====
__global__ __launch_bounds__(256,1) void smatT_kernel(
        const float* __restrict__ Wq, const float* __restrict__ Wk) {
    float* sG  = dsm;                  // [64][196]
    float* sT  = dsm + 64*196;         // [64][196]
    float* sWq = sT + 64*196;          // [64][68]  Wq^T (c-major)
    float* sWk = sWq + 64*68;          // [48][197]
    __shared__ float redS[8], redQ[8];
    int bh = blockIdx.x, tile = blockIdx.y;
    int b = bh >> 2, h = bh & 3;
    int tid = threadIdx.x;
    for (int i = tid; i < GSZ; i += 256) {
        int c = i / KVd, k = i % KVd;
        sG[c*196 + k] = g_G[(size_t)b*GSZ + i];
    }
    for (int i = tid; i < C1d*C1d; i += 256) {
        int d = i >> 6, c = i & 63;
        sWq[c*68 + d] = Wq[(size_t)h*C1d*C1d + i];
    }
    for (int i = tid; i < 48*KVd; i += 256) {
        int r = i / KVd, k = i % KVd;
        sWk[r*197 + k] = Wk[(size_t)h*KVd*KVd + (tile*48 + r)*KVd + k];
    }
    __syncthreads();
    int x = tid & 15, y = tid >> 4;
    {
        int ds = y*4, ks = x*12;
        float acc[4][12];
        #pragma unroll
        for (int j = 0; j < 4; j++)
            #pragma unroll
            for (int l = 0; l < 12; l++) acc[j][l] = 0.f;
        for (int c = 0; c < C1d; c++) {
            float wf[4];
            #pragma unroll
            for (int j = 0; j < 4; j++) wf[j] = sWq[c*68 + ds + j];
            const float4* gp = (const float4*)(sG + c*196 + ks);
            float4 g0 = gp[0], g1 = gp[1], g2 = gp[2];
            float gf[12] = {g0.x,g0.y,g0.z,g0.w, g1.x,g1.y,g1.z,g1.w, g2.x,g2.y,g2.z,g2.w};
            #pragma unroll
            for (int j = 0; j < 4; j++)
                #pragma unroll
                for (int l = 0; l < 12; l++) acc[j][l] += wf[j]*gf[l];
        }
        #pragma unroll
        for (int j = 0; j < 4; j++)
            #pragma unroll
            for (int l = 0; l < 12; l++) sT[(ds+j)*196 + ks + l] = acc[j][l];
    }
    __syncthreads();
    const float scale = 0.0721687836487f;   // 1/sqrt(192)
    int cs = y*4, kl = x*3;
    float acc2[4][3];
    #pragma unroll
    for (int j = 0; j < 4; j++)
        #pragma unroll
        for (int l = 0; l < 3; l++) acc2[j][l] = 0.f;
    for (int kp = 0; kp < KVd; kp++) {
        float tf[4], wf[3];
        #pragma unroll
        for (int j = 0; j < 4; j++) tf[j] = sT[(cs+j)*196 + kp];
        #pragma unroll
        for (int l = 0; l < 3; l++) wf[l] = sWk[(kl+l)*197 + kp];
        #pragma unroll
        for (int j = 0; j < 4; j++)
            #pragma unroll
            for (int l = 0; l < 3; l++) acc2[j][l] += tf[j]*wf[l];
    }
    float lsum = 0.f, lsq = 0.f;
    float* out = g_S + (size_t)bh*GSZ;
    #pragma unroll
    for (int j = 0; j < 4; j++)
        #pragma unroll
        for (int l = 0; l < 3; l++) {
            float v = acc2[j][l]*scale;
            out[(cs+j)*KVd + tile*48 + kl + l] = v;
            lsum += v; lsq += v*v;
        }
    int w = tid >> 5, lane = tid & 31;
    #pragma unroll
    for (int o = 16; o > 0; o >>= 1) {
        lsum += __shfl_down_sync(0xffffffffu, lsum, o);
        lsq  += __shfl_down_sync(0xffffffffu, lsq, o);
    }
    if (lane == 0) { redS[w] = lsum; redQ[w] = lsq; }
    __syncthreads();
    if (tid == 0) {
        float s = 0.f, q = 0.f;
        #pragma unroll
        for (int i = 0; i < 8; i++) { s += redS[i]; q += redQ[i]; }
        g_pstats[bh*4 + tile] = make_float2(s, q);
    }
}

// ============ 4) fused InstanceNorm + softmax + Pp-tile = probs @ Wv ========
__global__ __launch_bounds__(256,1) void pmat_kernel(const float* __restrict__ Wv) {
    float* sS = dsm;                   // [64][196] scores -> probs
    float* sV = dsm + 64*196;          // [192][52]
    __shared__ float s_m, s_rs;
    int bh = blockIdx.x, h = bh & 3, tile = blockIdx.y;
    int tid = threadIdx.x;
    for (int i = tid; i < GSZ; i += 256) {
        int c = i / KVd, k = i % KVd;
        sS[c*196 + k] = g_S[(size_t)bh*GSZ + i];
    }
    for (int i = tid; i < KVd*48; i += 256) {
        int k = i / 48, col = i % 48;
        sV[k*52 + col] = Wv[(size_t)h*KVd*KVd + k*KVd + tile*48 + col];
    }
    if (tid == 0) {
        float s = 0.f, q = 0.f;
        #pragma unroll
        for (int t = 0; t < 4; t++) {
            float2 p = g_pstats[bh*4 + t];
            s += p.x; q += p.y;
        }
        float m = s * (1.f/GSZ);
        float v = q * (1.f/GSZ) - m*m;
        s_m = m; s_rs = rsqrtf(v + 1e-5f);
    }
    __syncthreads();
    float mean = s_m, rs = s_rs;
    int w = tid >> 5, lane = tid & 31;
    for (int r = w; r < C1d; r += 8) {
        float vals[6];
        float mx = -1e30f;
        #pragma unroll
        for (int mm = 0; mm < 6; mm++) {
            vals[mm] = (sS[r*196 + lane + 32*mm] - mean) * rs;
            mx = fmaxf(mx, vals[mm]);
        }
        #pragma unroll
        for (int o = 16; o > 0; o >>= 1) mx = fmaxf(mx, __shfl_xor_sync(0xffffffffu, mx, o));
        float es = 0.f;
        #pragma unroll
        for (int mm = 0; mm < 6; mm++) { vals[mm] = __expf(vals[mm] - mx); es += vals[mm]; }
        #pragma unroll
        for (int o = 16; o > 0; o >>= 1) es += __shfl_xor_sync(0xffffffffu, es, o);
        float inv = 1.f / es;
        #pragma unroll
        for (int mm = 0; mm < 6; mm++) sS[r*196 + lane + 32*mm] = vals[mm] * inv;
    }
    __syncthreads();
    int x = tid & 15, y = tid >> 4;
    int cs = y*4, kl = x*3;
    float acc[4][3];
    #pragma unroll
    for (int j = 0; j < 4; j++)
        #pragma unroll
        for (int l = 0; l < 3; l++) acc[j][l] = 0.f;
    for (int kp = 0; kp < KVd; kp++) {
        float pf[4], vf[3];
        #pragma unroll
        for (int j = 0; j < 4; j++) pf[j] = sS[(cs+j)*196 + kp];
        #pragma unroll
        for (int l = 0; l < 3; l++) vf[l] = sV[kp*52 + kl + l];
        #pragma unroll
        for (int j = 0; j < 4; j++)
            #pragma unroll
            for (int l = 0; l < 3; l++) acc[j][l] += pf[j]*vf[l];
    }
    float* out = g_Pp + (size_t)bh*GSZ;
    #pragma unroll
    for (int j = 0; j < 4; j++)
        #pragma unroll
        for (int l = 0; l < 3; l++)
            out[(cs+j)*KVd + tile*48 + kl + l] = acc[j][l];
}

// ============ 5) M[b] = Wout @ mean_h(Pp) ============
__global__ __launch_bounds__(256,1) void mmat_kernel(const float* __restrict__ Wout) {
    float* sP = dsm;                 // [64][200]
    float* sW = dsm + 64*200;        // [64][64]
    int b = blockIdx.x;
    int tid = threadIdx.x;
    for (int i = tid; i < GSZ; i += 256) {
        int c = i / KVd, k = i % KVd;
        float sum = g_Pp[(size_t)(b*Hh+0)*GSZ + i] + g_Pp[(size_t)(b*Hh+1)*GSZ + i]
                  + g_Pp[(size_t)(b*Hh+2)*GSZ + i] + g_Pp[(size_t)(b*Hh+3)*GSZ + i];
        sP[c*200 + k] = sum * 0.25f;
    }
    for (int i = tid; i < C1d*C1d; i += 256) sW[i] = Wout[i];
    __syncthreads();
    int x = tid & 15, y = tid >> 4;
    int ds = y*4, ks = x*12;
    float acc[4][12];
    #pragma unroll
    for (int j = 0; j < 4; j++)
        #pragma unroll
        for (int l = 0; l < 12; l++) acc[j][l] = 0.f;
    for (int c = 0; c < 64; c++) {
        float wf[4], pf[12];
        #pragma unroll
        for (int j = 0; j < 4; j++) wf[j] = sW[(ds+j)*C1d + c];
        #pragma unroll
        for (int l = 0; l < 12; l++) pf[l] = sP[c*200 + ks + l];
        #pragma unroll
        for (int j = 0; j < 4; j++)
            #pragma unroll
            for (int l = 0; l < 12; l++) acc[j][l] += wf[j]*pf[l];
    }
    float* out = g_M + (size_t)b*GSZ;
    #pragma unroll
    for (int j = 0; j < 4; j++)
        #pragma unroll
        for (int l = 0; l < 12; l++) out[(ds+j)*KVd + ks + l] = acc[j][l];
}

// ============ 6) fused tail (tf32 mma): cx = emb1 + ea@M^T ; out = FFN + cx ==
__device__ __forceinline__ float gelu_exact(float x) {
    return 0.5f * x * (1.f + erff(x * 0.70710678118654752f));
}

// smem float offsets
#define T_HS   0                      /* Hs [64][260]=16640 ; alias sEA [64][196]=12544 */
#define T_W1   16640                  /* W1 [64][260]=16640 ; alias sMt [192][68]=13056 */
#define T_W2   33280                  /* W2 [256][68]=17408 */
#define T_XN   50688                  /* Xn [64][68] =4352  */
#define T_TOT  55040                  /* *4 = 220160 B */

__global__ __launch_bounds__(256,1) void tail_kernel(
        const float* __restrict__ emb1,
        const float* __restrict__ fc1w, const float* __restrict__ fc1b,
        const float* __restrict__ fc2w, const float* __restrict__ fc2b,
        const float* __restrict__ fg, const float* __restrict__ fb,
        float* __restrict__ out) {
    float* sEA = dsm + T_HS;           // [64][196]
    float* sMt = dsm + T_W1;           // [192][68]  M^T (k-major rows)
    float* W2s = dsm + T_W2;           // [256][68]  fc2^T (k-major rows)
    float* W1s = dsm + T_W1;           // [64][260]  fc1^T (k-major rows, after octx)
    float* Hs  = dsm + T_HS;           // [64][260]  (after octx)
    float* Xn  = dsm + T_XN;           // [64][68]
    __shared__ float ms[64], rss[64];
    int ch = blockIdx.x, b = blockIdx.y;
    int base = b*Nn + ch*64;
    int tid = threadIdx.x;
    int w = tid >> 5, lane = tid & 31;
    int gid = lane >> 2, tig = lane & 3;
    int wr = w >> 2, wc = w & 3;       // warp grid 2 x 4

    for (int i = tid; i < 64*KVd; i += 256) {
        int r = i / KVd, k = i % KVd;
        sEA[r*196 + k] = g_ea[(size_t)base*KVd + i];
    }
    for (int i = tid; i < GSZ; i += 256) {
        int c = i / KVd, k = i % KVd;
        sMt[k*68 + c] = g_M[(size_t)b*GSZ + i];
    }
    for (int i = tid; i < C1d*MLPd; i += 256) {
        int c = i >> 8, k = i & 255;
        W2s[k*68 + c] = fc2w[i];
    }
    __syncthreads();

    // ---- octx: C[64,64] = EA @ M^T; warp tile 32 rows x 16 cols ----
    float cx[2][2][4];
    {
        float cacc[2][2][4];
        #pragma unroll
        for (int i = 0; i < 2; i++)
            #pragma unroll
            for (int j = 0; j < 2; j++)
                #pragma unroll
                for (int q = 0; q < 4; q++) cacc[i][j][q] = 0.f;
        for (int ks = 0; ks < KVd; ks += 8) {
            uint32_t a[2][4], bb[2][2];
            #pragma unroll
            for (int i = 0; i < 2; i++) {
                int r0 = wr*32 + i*16;
                a[i][0] = f2tf32(sEA[(r0+gid)*196 + ks+tig]);
                a[i][1] = f2tf32(sEA[(r0+8+gid)*196 + ks+tig]);
                a[i][2] = f2tf32(sEA[(r0+gid)*196 + ks+tig+4]);
                a[i][3] = f2tf32(sEA[(r0+8+gid)*196 + ks+tig+4]);
            }
            #pragma unroll
            for (int j = 0; j < 2; j++) {
                int c0 = wc*16 + j*8;
                bb[j][0] = f2tf32(sMt[(ks+tig)*68 + c0+gid]);
                bb[j][1] = f2tf32(sMt[(ks+tig+4)*68 + c0+gid]);
            }
            #pragma unroll
            for (int i = 0; i < 2; i++)
                #pragma unroll
                for (int j = 0; j < 2; j++)
                    mma_tf32(cacc[i][j], a[i], bb[j]);
        }
        #pragma unroll
        for (int i = 0; i < 2; i++) {
            int r_lo = wr*32 + i*16 + gid, r_hi = r_lo + 8;
            #pragma unroll
            for (int j = 0; j < 2; j++) {
                int c0 = wc*16 + j*8 + 2*tig;
                float2 e0 = *(const float2*)(emb1 + (size_t)(base+r_lo)*C1d + c0);
                float2 e1 = *(const float2*)(emb1 + (size_t)(base+r_hi)*C1d + c0);
                cx[i][j][0] = cacc[i][j][0] + e0.x;
                cx[i][j][1] = cacc[i][j][1] + e0.y;
                cx[i][j][2] = cacc[i][j][2] + e1.x;
                cx[i][j][3] = cacc[i][j][3] + e1.y;
                *(float2*)(Xn + r_lo*68 + c0) = make_float2(cx[i][j][0], cx[i][j][1]);
                *(float2*)(Xn + r_hi*68 + c0) = make_float2(cx[i][j][2], cx[i][j][3]);
            }
        }
    }
    __syncthreads();
    // load W1 (k-major, overwrites sMt); LN stats
    for (int i = tid; i < MLPd*C1d; i += 256) {
        int d = i >> 6, k = i & 63;
        W1s[k*260 + d] = fc1w[i];
    }
    if (tid < 64) {
        float s = 0.f, q = 0.f;
        const float* row = Xn + tid*68;
        #pragma unroll 8
        for (int c = 0; c < C1d; c++) { float v = row[c]; s += v; q += v*v; }
        float m = s * (1.f/C1d);
        float v = q * (1.f/C1d) - m*m;
        ms[tid] = m; rss[tid] = rsqrtf(v + 1e-6f);
    }
    __syncthreads();
    for (int i = tid; i < 64*C1d; i += 256) {
        int r = i >> 6, c = i & 63;
        Xn[r*68 + c] = (Xn[r*68 + c] - ms[r]) * rss[r] * __ldg(fg + c) + __ldg(fb + c);
    }
    __syncthreads();

    // ---- fc1 + gelu: H[64,256] = Xn @ W1^T; warp tile 32 rows x 64 cols ----
    {
        float h[2][8][4];
        #pragma unroll
        for (int i = 0; i < 2; i++)
            #pragma unroll
            for (int j = 0; j < 8; j++)
                #pragma unroll
                for (int q = 0; q < 4; q++) h[i][j][q] = 0.f;
        for (int ks = 0; ks < C1d; ks += 8) {
            uint32_t a[2][4], bb[8][2];
            #pragma unroll
            for (int i = 0; i < 2; i++) {
                int r0 = wr*32 + i*16;
                a[i][0] = f2tf32(Xn[(r0+gid)*68 + ks+tig]);
                a[i][1] = f2tf32(Xn[(r0+8+gid)*68 + ks+tig]);
                a[i][2] = f2tf32(Xn[(r0+gid)*68 + ks+tig+4]);
                a[i][3] = f2tf32(Xn[(r0+8+gid)*68 + ks+tig+4]);
            }
            #pragma unroll
            for (int j = 0; j < 8; j++) {
                int c0 = wc*64 + j*8;
                bb[j][0] = f2tf32(W1s[(ks+tig)*260 + c0+gid]);
                bb[j][1] = f2tf32(W1s[(ks+tig+4)*260 + c0+gid]);
            }
            #pragma unroll
            for (int i = 0; i < 2; i++)
                #pragma unroll
                for (int j = 0; j < 8; j++)
                    mma_tf32(h[i][j], a[i], bb[j]);
        }
        __syncthreads();   // done reading sEA-region? (Hs aliases sEA; writes below)
        #pragma unroll
        for (int i = 0; i < 2; i++) {
            int r_lo = wr*32 + i*16 + gid, r_hi = r_lo + 8;
            #pragma unroll
            for (int j = 0; j < 8; j++) {
                int c0 = wc*64 + j*8 + 2*tig;
                float2 bj = *(const float2*)(fc1b + c0);
                *(float2*)(Hs + r_lo*260 + c0) =
                    make_float2(gelu_exact(h[i][j][0] + bj.x), gelu_exact(h[i][j][1] + bj.y));
                *(float2*)(Hs + r_hi*260 + c0) =
                    make_float2(gelu_exact(h[i][j][2] + bj.x), gelu_exact(h[i][j][3] + bj.y));
            }
        }
    }
    __syncthreads();

    // ---- fc2 + bias + residual: OUT[64,64] = H @ W2^T + b2 + cx ----
    {
        float oacc[2][2][4];
        #pragma unroll
        for (int i = 0; i < 2; i++)
            #pragma unroll
            for (int j = 0; j < 2; j++)
                #pragma unroll
                for (int q = 0; q < 4; q++) oacc[i][j][q] = 0.f;
        for (int ks = 0; ks < MLPd; ks += 8) {
            uint32_t a[2][4], bb[2][2];
            #pragma unroll
            for (int i = 0; i < 2; i++) {
                int r0 = wr*32 + i*16;
                a[i][0] = f2tf32(Hs[(r0+gid)*260 + ks+tig]);
                a[i][1] = f2tf32(Hs[(r0+8+gid)*260 + ks+tig]);
                a[i][2] = f2tf32(Hs[(r0+gid)*260 + ks+tig+4]);
                a[i][3] = f2tf32(Hs[(r0+8+gid)*260 + ks+tig+4]);
            }
            #pragma unroll
            for (int j = 0; j < 2; j++) {
                int c0 = wc*16 + j*8;
                bb[j][0] = f2tf32(W2s[(ks+tig)*68 + c0+gid]);
                bb[j][1] = f2tf32(W2s[(ks+tig+4)*68 + c0+gid]);
            }
            #pragma unroll
            for (int i = 0; i < 2; i++)
                #pragma unroll
                for (int j = 0; j < 2; j++)
                    mma_tf32(oacc[i][j], a[i], bb[j]);
        }
        #pragma unroll
        for (int i = 0; i < 2; i++) {
            int r_lo = wr*32 + i*16 + gid, r_hi = r_lo + 8;
            #pragma unroll
            for (int j = 0; j < 2; j++) {
                int c0 = wc*16 + j*8 + 2*tig;
                float2 b2 = *(const float2*)(fc2b + c0);
                float2 o0, o1;
                o0.x = oacc[i][j][0] + b2.x + cx[i][j][0];
                o0.y = oacc[i][j][1] + b2.y + cx[i][j][1];
                o1.x = oacc[i][j][2] + b2.x + cx[i][j][2];
                o1.y = oacc[i][j][3] + b2.y + cx[i][j][3];
                *(float2*)(out + (size_t)(base+r_lo)*C1d + c0) = o0;
                *(float2*)(out + (size_t)(base+r_hi)*C1d + c0) = o1;
            }
        }
    }
}

// ---------------- launch ----------------
extern "C" void kernel_launch(void* const* d_in, const int* in_sizes, int n_in,
                              void* d_out, int out_size) {
    const float* emb1   = (const float*)d_in[0];
    const float* emb2   = (const float*)d_in[1];
    const float* Wq     = (const float*)d_in[2];
    const float* Wk     = (const float*)d_in[3];
    const float* Wv     = (const float*)d_in[4];
    const float* Wout   = (const float*)d_in[5];
    const float* ln1_g  = (const float*)d_in[6];
    const float* ln1_b  = (const float*)d_in[7];
    const float* lnA_g  = (const float*)d_in[8];
    const float* lnA_b  = (const float*)d_in[9];
    const float* ffn_g  = (const float*)d_in[10];
    const float* ffn_b  = (const float*)d_in[11];
    const float* fc1_w  = (const float*)d_in[12];
    const float* fc1_b  = (const float*)d_in[13];
    const float* fc2_w  = (const float*)d_in[14];
    const float* fc2_b  = (const float*)d_in[15];
    float* out = (float*)d_out;

    const int smem_gmatln = (64*193 + 64*65) * 4;                    // 66048
    const int smem_smatT  = (64*196 + 64*196 + 64*68 + 48*197) * 4;  // 155584
    const int smem_pmat   = (64*196 + 192*52) * 4;                   // 90112
    const int smem_mmat   = (64*200 + 64*64) * 4;                    // 67584
    const int smem_tail   = T_TOT * 4;                               // 220160

    cudaFuncSetAttribute(gmatln_kernel, cudaFuncAttributeMaxDynamicSharedMemorySize, smem_gmatln);
    cudaFuncSetAttribute(smatT_kernel,  cudaFuncAttributeMaxDynamicSharedMemorySize, smem_smatT);
    cudaFuncSetAttribute(pmat_kernel,   cudaFuncAttributeMaxDynamicSharedMemorySize, smem_pmat);
    cudaFuncSetAttribute(mmat_kernel,   cudaFuncAttributeMaxDynamicSharedMemorySize, smem_mmat);
    cudaFuncSetAttribute(tail_kernel,   cudaFuncAttributeMaxDynamicSharedMemorySize, smem_tail);

    gmatln_kernel<<<dim3(NCH, Bq), 256, smem_gmatln>>>(emb1, emb2, ln1_g, ln1_b, lnA_g, lnA_b);
    gred_kernel<<<(Bq*GSZ)/256, 256>>>();
    smatT_kernel<<<dim3(Bq*Hh, 4), 256, smem_smatT>>>(Wq, Wk);
    pmat_kernel<<<dim3(Bq*Hh, 4), 256, smem_pmat>>>(Wv);
    mmat_kernel<<<Bq, 256, smem_mmat>>>(Wout);
    tail_kernel<<<dim3(NCH, Bq), 256, smem_tail>>>(emb1, fc1_w, fc1_b, fc2_w, fc2_b, ffn_g, ffn_b, out);
}

// round 6
// speedup vs baseline: 1.6294x; 1.2743x over previous
#include <cuda_runtime.h>
#include <math.h>
#include <stdint.h>

#define Bq   8
#define Nn   3136
#define C1d  64
#define C2d  128
#define KVd  192
#define Hh   4
#define MLPd 256
#define NROW (Bq*Nn)     /* 25088 */
#define NCH  49          /* 3136 / 64 */
#define GSZ  (C1d*KVd)   /* 12288 */

// ---------------- scratch (device globals; no allocation) ----------------
__device__ float g_ea[NROW*KVd];          // 19.3 MB  LN(concat) rows
__device__ float g_Gpart[Bq*NCH*GSZ];     // 19.3 MB  per-chunk partials of G
__device__ float g_G[Bq*GSZ];             //  G[b] = cx1^T @ ea
__device__ float g_S[Bq*Hh*GSZ];          //  scores (scaled, pre-IN)
__device__ float2 g_pstats[Bq*Hh*4];      //  per-tile (sum, sumsq) of scores
__device__ float g_Pp[Bq*Hh*GSZ];         //  probs @ Wv (per head)
__device__ float g_M[Bq*GSZ];             //  M[b] = Wout @ Pbar

extern __shared__ float dsm[];

// ---------------- tf32 mma helpers ----------------
__device__ __forceinline__ uint32_t f2tf32(float f) {
    uint32_t u;
    asm("cvt.rna.tf32.f32 %0, %1;" : "=r"(u) : "f"(f));
    return u;
}
__device__ __forceinline__ void mma_tf32(float* c, const uint32_t* a, const uint32_t* b) {
    asm volatile("mma.sync.aligned.m16n8k8.row.col.f32.tf32.tf32.f32 "
        "{%0,%1,%2,%3}, {%4,%5,%6,%7}, {%8,%9}, {%0,%1,%2,%3};"
        : "+f"(c[0]), "+f"(c[1]), "+f"(c[2]), "+f"(c[3])
        : "r"(a[0]), "r"(a[1]), "r"(a[2]), "r"(a[3]), "r"(b[0]), "r"(b[1]));
}

// ============ 1) fused dual-LayerNorm + G partial (tf32 mma) ============
// grid (49, 8), 256 threads
__global__ __launch_bounds__(256,2) void gmatln_kernel(
        const float* __restrict__ emb1, const float* __restrict__ emb2,
        const float* __restrict__ g1, const float* __restrict__ b1,
        const float* __restrict__ gA, const float* __restrict__ bA) {
    float* sE = dsm;                 // [64][193] raw -> normalized ea  (rows r, cols k2)
    float* sC = dsm + 64*193;        // [64][65]  cx1 (rows r, cols c)
    __shared__ float m1s[64], r1s[64], mAs[64], rAs[64];
    int ch = blockIdx.x, b = blockIdx.y;
    int base = b*Nn + ch*64;
    int tid = threadIdx.x;
    for (int i = tid; i < 64*KVd; i += 256) {
        int r = i / KVd, c = i % KVd;
        float v = (c < C1d) ? emb1[(size_t)(base+r)*C1d + c]
                            : emb2[(size_t)(base+r)*C2d + (c - C1d)];
        sE[r*193 + c] = v;
    }
    __syncthreads();
    if (tid < 64) {
        float s1 = 0.f, q1 = 0.f, s2 = 0.f, q2 = 0.f;
        const float* row = sE + tid*193;
        #pragma unroll 8
        for (int c = 0; c < C1d; c++)  { float v = row[c]; s1 += v; q1 += v*v; }
        #pragma unroll 8
        for (int c = C1d; c < KVd; c++){ float v = row[c]; s2 += v; q2 += v*v; }
        float m1 = s1 * (1.f/C1d);
        float v1 = q1 * (1.f/C1d) - m1*m1;
        m1s[tid] = m1; r1s[tid] = rsqrtf(v1 + 1e-6f);
        float mA = (s1+s2) * (1.f/KVd);
        float vA = (q1+q2) * (1.f/KVd) - mA*mA;
        mAs[tid] = mA; rAs[tid] = rsqrtf(vA + 1e-6f);
    }
    __syncthreads();
    for (int i = tid; i < 64*KVd; i += 256) {
        int r = i / KVd, c = i % KVd;
        float v = sE[r*193 + c];
        float ea = (v - mAs[r]) * rAs[r] * __ldg(gA + c) + __ldg(bA + c);
        sE[r*193 + c] = ea;
        g_ea[(size_t)(base+r)*KVd + c] = ea;
        if (c < C1d)
            sC[r*65 + c] = (v - m1s[r]) * r1s[r] * __ldg(g1 + c) + __ldg(b1 + c);
    }
    __syncthreads();
    // Gpart[c, k2] = sum_r cx1[r][c] * ea[r][k2]   (m=64 c, n=192 k2, k=64 r)
    int w = tid >> 5, lane = tid & 31;
    int gid = lane >> 2, tig = lane & 3;
    int wr = w >> 2, wc = w & 3;       // 2 x 4 warps; tile 32m x 48n
    float cacc[2][6][4];
    #pragma unroll
    for (int i = 0; i < 2; i++)
        #pragma unroll
        for (int j = 0; j < 6; j++)
            #pragma unroll
            for (int q = 0; q < 4; q++) cacc[i][j][q] = 0.f;
    for (int ks = 0; ks < C1d; ks += 8) {
        uint32_t a[2][4], bb[6][2];
        #pragma unroll
        for (int i = 0; i < 2; i++) {
            int m0 = wr*32 + i*16;
            a[i][0] = f2tf32(sC[(ks+tig)*65 + m0+gid]);
            a[i][1] = f2tf32(sC[(ks+tig)*65 + m0+8+gid]);
            a[i][2] = f2tf32(sC[(ks+tig+4)*65 + m0+gid]);
            a[i][3] = f2tf32(sC[(ks+tig+4)*65 + m0+8+gid]);
        }
        #pragma unroll
        for (int j = 0; j < 6; j++) {
            int n0 = wc*48 + j*8;
            bb[j][0] = f2tf32(sE[(ks+tig)*193 + n0+gid]);
            bb[j][1] = f2tf32(sE[(ks+tig+4)*193 + n0+gid]);
        }
        #pragma unroll
        for (int i = 0; i < 2; i++)
            #pragma unroll
            for (int j = 0; j < 6; j++)
                mma_tf32(cacc[i][j], a[i], bb[j]);
    }
    float* out = g_Gpart + (size_t)(b*NCH + ch)*GSZ;
    #pragma unroll
    for (int i = 0; i < 2; i++) {
        int r_lo = wr*32 + i*16 + gid, r_hi = r_lo + 8;
        #pragma unroll
        for (int j = 0; j < 6; j++) {
            int c0 = wc*48 + j*8 + 2*tig;
            *(float2*)(out + r_lo*KVd + c0) = make_float2(cacc[i][j][0], cacc[i][j][1]);
            *(float2*)(out + r_hi*KVd + c0) = make_float2(cacc[i][j][2], cacc[i][j][3]);
        }
    }
}

// ============ 2) reduce chunk partials ============
__global__ void gred_kernel() {
    int idx = blockIdx.x*256 + threadIdx.x;
    int b = idx / GSZ, e = idx % GSZ;
    const float* p = g_Gpart + (size_t)b*NCH*GSZ + e;
    float s = 0.f;
    #pragma unroll 7
    for (int ch = 0; ch < NCH; ch++) s += p[ch*GSZ];
    g_G[idx] = s;
}

// ============ 3) fused T=Wq@G, S = T@Wk^T/sqrt(KV) + partial stats (tf32) ===
// grid (32, 4), 256 threads
__global__ __launch_bounds__(256,1) void smatT_kernel(
        const float* __restrict__ Wq, const float* __restrict__ Wk) {
    float* sG  = dsm;                  // [64][196]  (rows c, cols k2)
    float* sT  = dsm + 64*196;         // [64][196]  (rows d, cols k2)
    float* sWq = sT + 64*196;          // [64][68]   Wq row-major padded
    float* sWk = sWq + 64*68;          // [192][52]  Wk^T tile (rows kp, cols j)
    __shared__ float redS[8], redQ[8];
    int bh = blockIdx.x, tile = blockIdx.y;
    int b = bh >> 2, h = bh & 3;
    int tid = threadIdx.x;
    for (int i = tid; i < GSZ; i += 256) {
        int c = i / KVd, k = i % KVd;
        sG[c*196 + k] = g_G[(size_t)b*GSZ + i];
    }
    for (int i = tid; i < C1d*C1d; i += 256) {
        int d = i >> 6, c = i & 63;
        sWq[d*68 + c] = Wq[(size_t)h*C1d*C1d + i];
    }
    for (int i = tid; i < 48*KVd; i += 256) {
        int j = i / KVd, kp = i % KVd;
        sWk[kp*52 + j] = Wk[(size_t)h*KVd*KVd + (tile*48 + j)*KVd + kp];
    }
    __syncthreads();
    int w = tid >> 5, lane = tid & 31;
    int gid = lane >> 2, tig = lane & 3;
    // Phase 1: T = Wq @ G  (m=64 d, n=192 k2, k=64 c);  warps 2x4, tile 32x48
    {
        int wr = w >> 2, wc = w & 3;
        float cacc[2][6][4];
        #pragma unroll
        for (int i = 0; i < 2; i++)
            #pragma unroll
            for (int j = 0; j < 6; j++)
                #pragma unroll
                for (int q = 0; q < 4; q++) cacc[i][j][q] = 0.f;
        for (int ks = 0; ks < C1d; ks += 8) {
            uint32_t a[2][4], bb[6][2];
            #pragma unroll
            for (int i = 0; i < 2; i++) {
                int m0 = wr*32 + i*16;
                a[i][0] = f2tf32(sWq[(m0+gid)*68 + ks+tig]);
                a[i][1] = f2tf32(sWq[(m0+8+gid)*68 + ks+tig]);
                a[i][2] = f2tf32(sWq[(m0+gid)*68 + ks+tig+4]);
                a[i][3] = f2tf32(sWq[(m0+8+gid)*68 + ks+tig+4]);
            }
            #pragma unroll
            for (int j = 0; j < 6; j++) {
                int n0 = wc*48 + j*8;
                bb[j][0] = f2tf32(sG[(ks+tig)*196 + n0+gid]);
                bb[j][1] = f2tf32(sG[(ks+tig+4)*196 + n0+gid]);
            }
            #pragma unroll
            for (int i = 0; i < 2; i++)
                #pragma unroll
                for (int j = 0; j < 6; j++)
                    mma_tf32(cacc[i][j], a[i], bb[j]);
        }
        #pragma unroll
        for (int i = 0; i < 2; i++) {
            int r_lo = wr*32 + i*16 + gid, r_hi = r_lo + 8;
            #pragma unroll
            for (int j = 0; j < 6; j++) {
                int c0 = wc*48 + j*8 + 2*tig;
                *(float2*)(sT + r_lo*196 + c0) = make_float2(cacc[i][j][0], cacc[i][j][1]);
                *(float2*)(sT + r_hi*196 + c0) = make_float2(cacc[i][j][2], cacc[i][j][3]);
            }
        }
    }
    __syncthreads();
    // Phase 2: S = T @ Wk^T * scale  (m=64 c, n=48 tile, k=192); warps 4x2, tile 16x24
    const float scale = 0.0721687836487f;   // 1/sqrt(192)
    float lsum = 0.f, lsq = 0.f;
    {
        int wr = w >> 1, wc = w & 1;
        int m0 = wr*16, n0 = wc*24;
        float cacc[3][4];
        #pragma unroll
        for (int j = 0; j < 3; j++)
            #pragma unroll
            for (int q = 0; q < 4; q++) cacc[j][q] = 0.f;
        for (int ks = 0; ks < KVd; ks += 8) {
            uint32_t a[4], bb[3][2];
            a[0] = f2tf32(sT[(m0+gid)*196 + ks+tig]);
            a[1] = f2tf32(sT[(m0+8+gid)*196 + ks+tig]);
            a[2] = f2tf32(sT[(m0+gid)*196 + ks+tig+4]);
            a[3] = f2tf32(sT[(m0+8+gid)*196 + ks+tig+4]);
            #pragma unroll
            for (int j = 0; j < 3; j++) {
                int c0 = n0 + j*8;
                bb[j][0] = f2tf32(sWk[(ks+tig)*52 + c0+gid]);
                bb[j][1] = f2tf32(sWk[(ks+tig+4)*52 + c0+gid]);
            }
            #pragma unroll
            for (int j = 0; j < 3; j++)
                mma_tf32(cacc[j], a, bb[j]);
        }
        float* out = g_S + (size_t)bh*GSZ;
        int r_lo = m0 + gid, r_hi = r_lo + 8;
        #pragma unroll
        for (int j = 0; j < 3; j++) {
            int c0 = tile*48 + n0 + j*8 + 2*tig;
            float v0 = cacc[j][0]*scale, v1 = cacc[j][1]*scale;
            float v2 = cacc[j][2]*scale, v3 = cacc[j][3]*scale;
            *(float2*)(out + r_lo*KVd + c0) = make_float2(v0, v1);
            *(float2*)(out + r_hi*KVd + c0) = make_float2(v2, v3);
            lsum += v0+v1+v2+v3;
            lsq  += v0*v0+v1*v1+v2*v2+v3*v3;
        }
    }
    #pragma unroll
    for (int o = 16; o > 0; o >>= 1) {
        lsum += __shfl_down_sync(0xffffffffu, lsum, o);
        lsq  += __shfl_down_sync(0xffffffffu, lsq, o);
    }
    if (lane == 0) { redS[w] = lsum; redQ[w] = lsq; }
    __syncthreads();
    if (tid == 0) {
        float s = 0.f, q = 0.f;
        #pragma unroll
        for (int i = 0; i < 8; i++) { s += redS[i]; q += redQ[i]; }
        g_pstats[bh*4 + tile] = make_float2(s, q);
    }
}

// ============ 4) fused IN + softmax + Pp = probs @ Wv (tf32) ========
// grid (32, 4), 256 threads
__global__ __launch_bounds__(256,2) void pmat_kernel(const float* __restrict__ Wv) {
    float* sS = dsm;                   // [64][196] scores -> probs
    float* sV = dsm + 64*196;          // [192][52]  Wv tile (rows kp, cols j)
    __shared__ float s_m, s_rs;
    int bh = blockIdx.x, h = bh & 3, tile = blockIdx.y;
    int tid = threadIdx.x;
    for (int i = tid; i < GSZ; i += 256) {
        int c = i / KVd, k = i % KVd;
        sS[c*196 + k] = g_S[(size_t)bh*GSZ + i];
    }
    for (int i = tid; i < KVd*48; i += 256) {
        int k = i / 48, col = i % 48;
        sV[k*52 + col] = Wv[(size_t)h*KVd*KVd + k*KVd + tile*48 + col];
    }
    if (tid == 0) {
        float s = 0.f, q = 0.f;
        #pragma unroll
        for (int t = 0; t < 4; t++) {
            float2 p = g_pstats[bh*4 + t];
            s += p.x; q += p.y;
        }
        float m = s * (1.f/GSZ);
        float v = q * (1.f/GSZ) - m*m;
        s_m = m; s_rs = rsqrtf(v + 1e-5f);
    }
    __syncthreads();
    float mean = s_m, rs = s_rs;
    int w = tid >> 5, lane = tid & 31;
    for (int r = w; r < C1d; r += 8) {
        float vals[6];
        float mx = -1e30f;
        #pragma unroll
        for (int mm = 0; mm < 6; mm++) {
            vals[mm] = (sS[r*196 + lane + 32*mm] - mean) * rs;
            mx = fmaxf(mx, vals[mm]);
        }
        #pragma unroll
        for (int o = 16; o > 0; o >>= 1) mx = fmaxf(mx, __shfl_xor_sync(0xffffffffu, mx, o));
        float es = 0.f;
        #pragma unroll
        for (int mm = 0; mm < 6; mm++) { vals[mm] = __expf(vals[mm] - mx); es += vals[mm]; }
        #pragma unroll
        for (int o = 16; o > 0; o >>= 1) es += __shfl_xor_sync(0xffffffffu, es, o);
        float inv = 1.f / es;
        #pragma unroll
        for (int mm = 0; mm < 6; mm++) sS[r*196 + lane + 32*mm] = vals[mm] * inv;
    }
    __syncthreads();
    // Pp = probs @ Wv  (m=64 c, n=48, k=192); warps 4x2, tile 16x24
    int gid = lane >> 2, tig = lane & 3;
    int wr = w >> 1, wc = w & 1;
    int m0 = wr*16, n0 = wc*24;
    float cacc[3][4];
    #pragma unroll
    for (int j = 0; j < 3; j++)
        #pragma unroll
        for (int q = 0; q < 4; q++) cacc[j][q] = 0.f;
    for (int ks = 0; ks < KVd; ks += 8) {
        uint32_t a[4], bb[3][2];
        a[0] = f2tf32(sS[(m0+gid)*196 + ks+tig]);
        a[1] = f2tf32(sS[(m0+8+gid)*196 + ks+tig]);
        a[2] = f2tf32(sS[(m0+gid)*196 + ks+tig+4]);
        a[3] = f2tf32(sS[(m0+8+gid)*196 + ks+tig+4]);
        #pragma unroll
        for (int j = 0; j < 3; j++) {
            int c0 = n0 + j*8;
            bb[j][0] = f2tf32(sV[(ks+tig)*52 + c0+gid]);
            bb[j][1] = f2tf32(sV[(ks+tig+4)*52 + c0+gid]);
        }
        #pragma unroll
        for (int j = 0; j < 3; j++)
            mma_tf32(cacc[j], a, bb[j]);
    }
    float* out = g_Pp + (size_t)bh*GSZ;
    int r_lo = m0 + gid, r_hi = r_lo + 8;
    #pragma unroll
    for (int j = 0; j < 3; j++) {
        int c0 = tile*48 + n0 + j*8 + 2*tig;
        *(float2*)(out + r_lo*KVd + c0) = make_float2(cacc[j][0], cacc[j][1]);
        *(float2*)(out + r_hi*KVd + c0) = make_float2(cacc[j][2], cacc[j][3]);
    }
}

// ============ 5) M[b] = Wout @ mean_h(Pp) ============
__global__ __launch_bounds__(256,1) void mmat_kernel(const float* __restrict__ Wout) {
    float* sP = dsm;                 // [64][200]
    float* sW = dsm + 64*200;        // [64][64]
    int b = blockIdx.x;
    int tid = threadIdx.x;
    for (int i = tid; i < GSZ; i += 256) {
        int c = i / KVd, k = i % KVd;
        float sum = g_Pp[(size_t)(b*Hh+0)*GSZ + i] + g_Pp[(size_t)(b*Hh+1)*GSZ + i]
                  + g_Pp[(size_t)(b*Hh+2)*GSZ + i] + g_Pp[(size_t)(b*Hh+3)*GSZ + i];
        sP[c*200 + k] = sum * 0.25f;
    }
    for (int i = tid; i < C1d*C1d; i += 256) sW[i] = Wout[i];
    __syncthreads();
    int x = tid & 15, y = tid >> 4;
    int ds = y*4, ks = x*12;
    float acc[4][12];
    #pragma unroll
    for (int j = 0; j < 4; j++)
        #pragma unroll
        for (int l = 0; l < 12; l++) acc[j][l] = 0.f;
    for (int c = 0; c < 64; c++) {
        float wf[4], pf[12];
        #pragma unroll
        for (int j = 0; j < 4; j++) wf[j] = sW[(ds+j)*C1d + c];
        #pragma unroll
        for (int l = 0; l < 12; l++) pf[l] = sP[c*200 + ks + l];
        #pragma unroll
        for (int j = 0; j < 4; j++)
            #pragma unroll
            for (int l = 0; l < 12; l++) acc[j][l] += wf[j]*pf[l];
    }
    float* out = g_M + (size_t)b*GSZ;
    #pragma unroll
    for (int j = 0; j < 4; j++)
        #pragma unroll
        for (int l = 0; l < 12; l++) out[(ds+j)*KVd + ks + l] = acc[j][l];
}

// ============ 6) fused tail (tf32 mma, weights from gmem, 2 blocks/SM) ======
__device__ __forceinline__ float gelu_exact(float x) {
    return 0.5f * x * (1.f + erff(x * 0.70710678118654752f));
}

// smem float offsets
#define T_HS   0                      /* Hs [64][260]=16640 ; alias sEA [64][196]=12544 */
#define T_XN   16640                  /* Xn [64][68] =4352  */
#define T_TOT  20992                  /* *4 = 83968 B */

__global__ __launch_bounds__(256,2) void tail_kernel(
        const float* __restrict__ emb1,
        const float* __restrict__ fc1w, const float* __restrict__ fc1b,
        const float* __restrict__ fc2w, const float* __restrict__ fc2b,
        const float* __restrict__ fg, const float* __restrict__ fb,
        float* __restrict__ out) {
    float* sEA = dsm + T_HS;           // [64][196]
    float* Hs  = dsm + T_HS;           // [64][260]  (after octx)
    float* Xn  = dsm + T_XN;           // [64][68]
    __shared__ float ms[64], rss[64];
    int ch = blockIdx.x, b = blockIdx.y;
    int base = b*Nn + ch*64;
    int tid = threadIdx.x;
    int w = tid >> 5, lane = tid & 31;
    int gid = lane >> 2, tig = lane & 3;
    int wr = w >> 2, wc = w & 3;       // warp grid 2 x 4
    const float* Mb = g_M + (size_t)b*GSZ;

    for (int i = tid; i < 64*KVd; i += 256) {
        int r = i / KVd, k = i % KVd;
        sEA[r*196 + k] = g_ea[(size_t)base*KVd + i];
    }
    __syncthreads();

    // ---- octx: C[64,64] = EA @ M^T; warp tile 32 rows x 16 cols ----
    float cx[2][2][4];
    {
        float cacc[2][2][4];
        #pragma unroll
        for (int i = 0; i < 2; i++)
            #pragma unroll
            for (int j = 0; j < 2; j++)
                #pragma unroll
                for (int q = 0; q < 4; q++) cacc[i][j][q] = 0.f;
        for (int ks = 0; ks < KVd; ks += 8) {
            uint32_t a[2][4], bb[2][2];
            #pragma unroll
            for (int i = 0; i < 2; i++) {
                int r0 = wr*32 + i*16;
                a[i][0] = f2tf32(sEA[(r0+gid)*196 + ks+tig]);
                a[i][1] = f2tf32(sEA[(r0+8+gid)*196 + ks+tig]);
                a[i][2] = f2tf32(sEA[(r0+gid)*196 + ks+tig+4]);
                a[i][3] = f2tf32(sEA[(r0+8+gid)*196 + ks+tig+4]);
            }
            #pragma unroll
            for (int j = 0; j < 2; j++) {
                int c0 = wc*16 + j*8;
                bb[j][0] = f2tf32(__ldg(Mb + (c0+gid)*KVd + ks+tig));
                bb[j][1] = f2tf32(__ldg(Mb + (c0+gid)*KVd + ks+tig+4));
            }
            #pragma unroll
            for (int i = 0; i < 2; i++)
                #pragma unroll
                for (int j = 0; j < 2; j++)
                    mma_tf32(cacc[i][j], a[i], bb[j]);
        }
        #pragma unroll
        for (int i = 0; i < 2; i++) {
            int r_lo = wr*32 + i*16 + gid, r_hi = r_lo + 8;
            #pragma unroll
            for (int j = 0; j < 2; j++) {
                int c0 = wc*16 + j*8 + 2*tig;
                float2 e0 = *(const float2*)(emb1 + (size_t)(base+r_lo)*C1d + c0);
                float2 e1 = *(const float2*)(emb1 + (size_t)(base+r_hi)*C1d + c0);
                cx[i][j][0] = cacc[i][j][0] + e0.x;
                cx[i][j][1] = cacc[i][j][1] + e0.y;
                cx[i][j][2] = cacc[i][j][2] + e1.x;
                cx[i][j][3] = cacc[i][j][3] + e1.y;
                *(float2*)(Xn + r_lo*68 + c0) = make_float2(cx[i][j][0], cx[i][j][1]);
                *(float2*)(Xn + r_hi*68 + c0) = make_float2(cx[i][j][2], cx[i][j][3]);
            }
        }
    }
    __syncthreads();
    // LN stats
    if (tid < 64) {
        float s = 0.f, q = 0.f;
        const float* row = Xn + tid*68;
        #pragma unroll 8
        for (int c = 0; c < C1d; c++) { float v = row[c]; s += v; q += v*v; }
        float m = s * (1.f/C1d);
        float v = q * (1.f/C1d) - m*m;
        ms[tid] = m; rss[tid] = rsqrtf(v + 1e-6f);
    }
    __syncthreads();
    for (int i = tid; i < 64*C1d; i += 256) {
        int r = i >> 6, c = i & 63;
        Xn[r*68 + c] = (Xn[r*68 + c] - ms[r]) * rss[r] * __ldg(fg + c) + __ldg(fb + c);
    }
    __syncthreads();

    // ---- fc1 + gelu: H[64,256] = Xn @ W1^T; warp tile 32 rows x 64 cols ----
    {
        float h[2][8][4];
        #pragma unroll
        for (int i = 0; i < 2; i++)
            #pragma unroll
            for (int j = 0; j < 8; j++)
                #pragma unroll
                for (int q = 0; q < 4; q++) h[i][j][q] = 0.f;
        for (int ks = 0; ks < C1d; ks += 8) {
            uint32_t a[2][4], bb[8][2];
            #pragma unroll
            for (int i = 0; i < 2; i++) {
                int r0 = wr*32 + i*16;
                a[i][0] = f2tf32(Xn[(r0+gid)*68 + ks+tig]);
                a[i][1] = f2tf32(Xn[(r0+8+gid)*68 + ks+tig]);
                a[i][2] = f2tf32(Xn[(r0+gid)*68 + ks+tig+4]);
                a[i][3] = f2tf32(Xn[(r0+8+gid)*68 + ks+tig+4]);
            }
            #pragma unroll
            for (int j = 0; j < 8; j++) {
                int c0 = wc*64 + j*8;
                bb[j][0] = f2tf32(__ldg(fc1w + (c0+gid)*C1d + ks+tig));
                bb[j][1] = f2tf32(__ldg(fc1w + (c0+gid)*C1d + ks+tig+4));
            }
            #pragma unroll
            for (int i = 0; i < 2; i++)
                #pragma unroll
                for (int j = 0; j < 8; j++)
                    mma_tf32(h[i][j], a[i], bb[j]);
        }
        __syncthreads();   // sEA region dead; Hs writes below
        #pragma unroll
        for (int i = 0; i < 2; i++) {
            int r_lo = wr*32 + i*16 + gid, r_hi = r_lo + 8;
            #pragma unroll
            for (int j = 0; j < 8; j++) {
                int c0 = wc*64 + j*8 + 2*tig;
                float2 bj = *(const float2*)(fc1b + c0);
                *(float2*)(Hs + r_lo*260 + c0) =
                    make_float2(gelu_exact(h[i][j][0] + bj.x), gelu_exact(h[i][j][1] + bj.y));
                *(float2*)(Hs + r_hi*260 + c0) =
                    make_float2(gelu_exact(h[i][j][2] + bj.x), gelu_exact(h[i][j][3] + bj.y));
            }
        }
    }
    __syncthreads();

    // ---- fc2 + bias + residual: OUT[64,64] = H @ W2^T + b2 + cx ----
    {
        float oacc[2][2][4];
        #pragma unroll
        for (int i = 0; i < 2; i++)
            #pragma unroll
            for (int j = 0; j < 2; j++)
                #pragma unroll
                for (int q = 0; q < 4; q++) oacc[i][j][q] = 0.f;
        for (int ks = 0; ks < MLPd; ks += 8) {
            uint32_t a[2][4], bb[2][2];
            #pragma unroll
            for (int i = 0; i < 2; i++) {
                int r0 = wr*32 + i*16;
                a[i][0] = f2tf32(Hs[(r0+gid)*260 + ks+tig]);
                a[i][1] = f2tf32(Hs[(r0+8+gid)*260 + ks+tig]);
                a[i][2] = f2tf32(Hs[(r0+gid)*260 + ks+tig+4]);
                a[i][3] = f2tf32(Hs[(r0+8+gid)*260 + ks+tig+4]);
            }
            #pragma unroll
            for (int j = 0; j < 2; j++) {
                int c0 = wc*16 + j*8;
                bb[j][0] = f2tf32(__ldg(fc2w + (c0+gid)*MLPd + ks+tig));
                bb[j][1] = f2tf32(__ldg(fc2w + (c0+gid)*MLPd + ks+tig+4));
            }
            #pragma unroll
            for (int i = 0; i < 2; i++)
                #pragma unroll
                for (int j = 0; j < 2; j++)
                    mma_tf32(oacc[i][j], a[i], bb[j]);
        }
        #pragma unroll
        for (int i = 0; i < 2; i++) {
            int r_lo = wr*32 + i*16 + gid, r_hi = r_lo + 8;
            #pragma unroll
            for (int j = 0; j < 2; j++) {
                int c0 = wc*16 + j*8 + 2*tig;
                float2 b2 = *(const float2*)(fc2b + c0);
                float2 o0, o1;
                o0.x = oacc[i][j][0] + b2.x + cx[i][j][0];
                o0.y = oacc[i][j][1] + b2.y + cx[i][j][1];
                o1.x = oacc[i][j][2] + b2.x + cx[i][j][2];
                o1.y = oacc[i][j][3] + b2.y + cx[i][j][3];
                *(float2*)(out + (size_t)(base+r_lo)*C1d + c0) = o0;
                *(float2*)(out + (size_t)(base+r_hi)*C1d + c0) = o1;
            }
        }
    }
}

// ---------------- launch ----------------
extern "C" void kernel_launch(void* const* d_in, const int* in_sizes, int n_in,
                              void* d_out, int out_size) {
    const float* emb1   = (const float*)d_in[0];
    const float* emb2   = (const float*)d_in[1];
    const float* Wq     = (const float*)d_in[2];
    const float* Wk     = (const float*)d_in[3];
    const float* Wv     = (const float*)d_in[4];
    const float* Wout   = (const float*)d_in[5];
    const float* ln1_g  = (const float*)d_in[6];
    const float* ln1_b  = (const float*)d_in[7];
    const float* lnA_g  = (const float*)d_in[8];
    const float* lnA_b  = (const float*)d_in[9];
    const float* ffn_g  = (const float*)d_in[10];
    const float* ffn_b  = (const float*)d_in[11];
    const float* fc1_w  = (const float*)d_in[12];
    const float* fc1_b  = (const float*)d_in[13];
    const float* fc2_w  = (const float*)d_in[14];
    const float* fc2_b  = (const float*)d_in[15];
    float* out = (float*)d_out;

    const int smem_gmatln = (64*193 + 64*65) * 4;                    // 66048
    const int smem_smatT  = (64*196 + 64*196 + 64*68 + 192*52) * 4;  // 157696
    const int smem_pmat   = (64*196 + 192*52) * 4;                   // 90112
    const int smem_mmat   = (64*200 + 64*64) * 4;                    // 67584
    const int smem_tail   = T_TOT * 4;                               // 83968

    cudaFuncSetAttribute(gmatln_kernel, cudaFuncAttributeMaxDynamicSharedMemorySize, smem_gmatln);
    cudaFuncSetAttribute(smatT_kernel,  cudaFuncAttributeMaxDynamicSharedMemorySize, smem_smatT);
    cudaFuncSetAttribute(pmat_kernel,   cudaFuncAttributeMaxDynamicSharedMemorySize, smem_pmat);
    cudaFuncSetAttribute(mmat_kernel,   cudaFuncAttributeMaxDynamicSharedMemorySize, smem_mmat);
    cudaFuncSetAttribute(tail_kernel,   cudaFuncAttributeMaxDynamicSharedMemorySize, smem_tail);

    gmatln_kernel<<<dim3(NCH, Bq), 256, smem_gmatln>>>(emb1, emb2, ln1_g, ln1_b, lnA_g, lnA_b);
    gred_kernel<<<(Bq*GSZ)/256, 256>>>();
    smatT_kernel<<<dim3(Bq*Hh, 4), 256, smem_smatT>>>(Wq, Wk);
    pmat_kernel<<<dim3(Bq*Hh, 4), 256, smem_pmat>>>(Wv);
    mmat_kernel<<<Bq, 256, smem_mmat>>>(Wout);
    tail_kernel<<<dim3(NCH, Bq), 256, smem_tail>>>(emb1, fc1_w, fc1_b, fc2_w, fc2_b, ffn_g, ffn_b, out);
}